// round 8
// baseline (speedup 1.0000x reference)
#include <cuda_runtime.h>
#include <math.h>

#define Bn 4
#define Tn 2048
#define Dn 1024
#define Hn 16
#define HDn 64
#define En 16
#define Rn 64                     // Bn*En active rows
#define QK_SCALE 0.35355339059327373f   // hd^-0.25
#define SM_SCALE 0.125f                 // 1/sqrt(hd)

typedef unsigned long long u64;

// ---------------- scratch (static device globals; no allocation) ----------
__device__ float g_xn[Rn * Dn];
__device__ float g_q[Rn * Dn];
__device__ float g_k[Rn * Dn];
__device__ float g_v[Rn * Dn];
__device__ float g_ai1[Rn * Dn];
__device__ float g_ai2[Rn * Dn];
__device__ float g_diffsum;

// ---------------- helpers -------------------------------------------------
__device__ __forceinline__ float warpReduceSum(float v) {
#pragma unroll
    for (int o = 16; o > 0; o >>= 1) v += __shfl_xor_sync(0xffffffffu, v, o);
    return v;
}

__device__ __forceinline__ float blockReduce256(float v, float* sh) {
    __syncthreads();
    v = warpReduceSum(v);
    int wid = threadIdx.x >> 5;
    if ((threadIdx.x & 31) == 0) sh[wid] = v;
    __syncthreads();
    if (threadIdx.x < 32) {
        float t = (threadIdx.x < 8) ? sh[threadIdx.x] : 0.f;
        t = warpReduceSum(t);
        if (threadIdx.x == 0) sh[0] = t;
    }
    __syncthreads();
    return sh[0];
}

// packed fp32x2 FMA (sm_100+): d = a*b + d, lane-wise on a 64-bit pair
__device__ __forceinline__ void ffma2(u64& d, u64 a, u64 b) {
    asm("fma.rn.f32x2 %0, %1, %2, %0;" : "+l"(d) : "l"(a), "l"(b));
}
__device__ __forceinline__ u64 fadd2(u64 a, u64 b) {
    u64 r;
    asm("add.rn.f32x2 %0, %1, %2;" : "=l"(r) : "l"(a), "l"(b));
    return r;
}
__device__ __forceinline__ u64 pack2(float a, float b) {
    u64 r;
    asm("mov.b64 %0, {%1, %2};" : "=l"(r) : "f"(a), "f"(b));
    return r;
}
__device__ __forceinline__ float lo32(u64 v) { return ((float2*)&v)->x; }
__device__ __forceinline__ float hi32(u64 v) { return ((float2*)&v)->y; }
__device__ __forceinline__ u64 shfl64(u64 v, int src) {
    return __shfl_sync(0xffffffffu, v, src);
}

__device__ __forceinline__ unsigned smem_u32p(const void* p) {
    return (unsigned)__cvta_generic_to_shared(p);
}
__device__ __forceinline__ void cp16(unsigned dst, const void* src) {
    asm volatile("cp.async.cg.shared.global [%0], [%1], 16;" :: "r"(dst), "l"(src));
}
__device__ __forceinline__ void cp8(unsigned dst, const void* src) {
    asm volatile("cp.async.ca.shared.global [%0], [%1], 8;" :: "r"(dst), "l"(src));
}
__device__ __forceinline__ void cp_commit() {
    asm volatile("cp.async.commit_group;");
}
__device__ __forceinline__ void cp_wait0() {
    asm volatile("cp.async.wait_group 0;");
}
// vector float atomic add (sm_90+)
__device__ __forceinline__ void red4(float* p, float a, float b, float c, float d) {
    asm volatile("red.global.add.v4.f32 [%0], {%1,%2,%3,%4};"
                 :: "l"(p), "f"(a), "f"(b), "f"(c), "f"(d) : "memory");
}

// ======================= K1a: LN(64 rows) + accumulator inits =============
__global__ __launch_bounds__(256) void k_ln(
    const float* __restrict__ x, const float* __restrict__ lna,
    const float* __restrict__ bq, const float* __restrict__ bv) {
    if (blockIdx.x < Rn) {
        __shared__ float sh[8];
        if (blockIdx.x == 0 && threadIdx.x == 0) g_diffsum = 0.f;
        int r = blockIdx.x;
        int b = r >> 4, t = r & 15;
        const float* xr = x + ((size_t)(b * Tn + t)) * Dn;
        int tid = threadIdx.x;
        float v[4];
        float s = 0.f;
#pragma unroll
        for (int i = 0; i < 4; i++) { v[i] = xr[tid + i * 256]; s += v[i]; }
        s = blockReduce256(s, sh);
        float mean = s * (1.f / 1024.f);
        float sq = 0.f;
#pragma unroll
        for (int i = 0; i < 4; i++) { float d = v[i] - mean; sq += d * d; }
        sq = blockReduce256(sq, sh);
        float inv = rsqrtf(sq * (1.f / 1024.f) + 1e-5f);
#pragma unroll
        for (int i = 0; i < 4; i++) {
            int j = tid + i * 256;
            g_xn[r * Dn + j] = (v[i] - mean) * inv * lna[j];
        }
    } else {
        int r = blockIdx.x - Rn;
        int tid = threadIdx.x;
#pragma unroll
        for (int i = 0; i < 4; i++) {
            int j = tid + i * 256;
            g_q[r * Dn + j] = bq[j] * QK_SCALE;
            g_k[r * Dn + j] = 0.f;
            g_v[r * Dn + j] = bv[j];
        }
    }
}

// ======================= K1b: bo fill of whole output (side stream) =======
__global__ __launch_bounds__(256) void k_fill(
    const float* __restrict__ bo, float* __restrict__ out) {
    const float4* bo4 = (const float4*)bo;
    float4* o4 = (float4*)out;
    size_t total = (size_t)Bn * Tn * Dn / 4;
    size_t start = (size_t)blockIdx.x * 256 + threadIdx.x;
    size_t stride = (size_t)gridDim.x * 256;
    float4 v = bo4[start & 255];
    for (size_t i = start; i < total; i += stride) o4[i] = v;
}

// ======================= 64x128 FFMA2 GEMM tile core ======================
#define TK 64

__device__ __forceinline__ void stage_tile(
    const float* __restrict__ A, const float* __restrict__ W,
    int j0, int kb, float* sA, float* sW) {
    int tid = threadIdx.x;
#pragma unroll
    for (int c = tid; c < 64 * TK / 2; c += 128) {
        int r = c >> 5;
        int kf = (c & 31) * 2;
        int rg = r >> 3;
        int swz = ((rg & 3) * 8) | ((rg >> 2) * 2);
        cp8(smem_u32p(&sA[r * TK + (kf ^ swz)]),
            &A[(size_t)r * Dn + kb + kf]);
    }
#pragma unroll
    for (int c = tid; c < 128 * TK / 4; c += 128) {
        int r = c >> 4;
        int kf = (c & 15) * 4;
        cp16(smem_u32p(&sW[r * TK + kf]),
             &W[(size_t)(j0 + r) * Dn + kb + kf]);
    }
    cp_commit();
}

__device__ __forceinline__ void compute_tile(
    const float* sA, const float* sW, u64* acc, int rg, int cg) {
    int swz = ((rg & 3) * 8) | ((rg >> 2) * 2);
    const float* aBase = sA + rg * 8 * TK;
    const float* wBase = sW + cg * 8 * TK;
#pragma unroll 4
    for (int kk = 0; kk < TK; kk += 2) {
        int ka = kk ^ swz;
        u64 av[8], wv[8];
#pragma unroll
        for (int i = 0; i < 8; i++)
            av[i] = *(const u64*)&aBase[i * TK + ka];
#pragma unroll
        for (int j = 0; j < 8; j++)
            wv[j] = *(const u64*)&wBase[j * TK + kk];
#pragma unroll
        for (int i = 0; i < 8; i++)
#pragma unroll
            for (int j = 0; j < 8; j++) ffma2(acc[i * 8 + j], av[i], wv[j]);
    }
}
#define GEMM_SMEM ((64 + 128) * TK * 4)   // 49152 bytes

// ======================= K2: q,k,v GEMMs (k-split 16, red.v4) =============
__global__ __launch_bounds__(128) void k_qkv(
    const float* __restrict__ Wq, const float* __restrict__ Wk,
    const float* __restrict__ Wv) {
    extern __shared__ float sh[];
    float* sA = sh;
    float* sW = sh + 64 * TK;
    int m = blockIdx.z;
    const float* W = (m == 0) ? Wq : (m == 1) ? Wk : Wv;
    float* dst = (m == 0) ? g_q : (m == 1) ? g_k : g_v;
    float scale = (m == 2) ? 1.0f : QK_SCALE;
    int j0 = blockIdx.x * 128;
    int kb = blockIdx.y * TK;
    u64 acc[64] = {};
    stage_tile(g_xn, W, j0, kb, sA, sW);
    cp_wait0();
    __syncthreads();
    int tid = threadIdx.x, rg = tid & 7, cg = tid >> 3;
    compute_tile(sA, sW, acc, rg, cg);
    int c0 = j0 + cg * 8;
#pragma unroll
    for (int i = 0; i < 8; i++) {
        int row = rg * 8 + i;
        float v[8];
#pragma unroll
        for (int j = 0; j < 8; j++) {
            float2 f = *(float2*)&acc[i * 8 + j];
            v[j] = (f.x + f.y) * scale;
        }
        float* p = &dst[(size_t)row * Dn + c0];
        red4(p, v[0], v[1], v[2], v[3]);
        red4(p + 4, v[4], v[5], v[6], v[7]);
    }
}

// ======================= K3: warp-synchronous per-head iteration kernel ===
// 64 blocks (one per (b,h)), 256 threads = 8 warps. Warp w owns e-rows
// {w, w+8}. qcur/kcur/vcur live in registers (one f32x2 pair per lane).
// Per iteration: three 64x64 GEMVs via shuffle-broadcast, LN via shuffles,
// k/v published to double-buffered smem, ONE __syncthreads, then
// logits/softmax/AV warp-local. smem u64 arrays, row stride 33 (8B aligned,
// <=2-way bank conflicts; AV reads conflict-free).
#define WQ_OFF 0
#define WK_OFF 2112            // 64*33
#define WV_OFF 4224
#define KSB_OFF 6336           // 2 bufs * 528
#define VLB_OFF 7392
#define KHEADS_SMEM ((7392 + 2 * 528) * 8)   // 67584 bytes

// y pair for rows j=2l,2l+1 of W (stride-33 u64 smem), x broadcast by shfl
#define GEMV2(wbase, x0, x1, a00, a01, a10, a11)                         \
    {                                                                     \
        a00 = 0; a01 = 0; a10 = 0; a11 = 0;                               \
        const u64* w0p = (wbase) + (2 * lane) * 33;                       \
        const u64* w1p = w0p + 33;                                        \
        _Pragma("unroll 8")                                               \
        for (int s = 0; s < 32; s++) {                                    \
            u64 xb0 = shfl64(x0, s);                                      \
            u64 xb1 = shfl64(x1, s);                                      \
            u64 w0 = w0p[s], w1 = w1p[s];                                 \
            ffma2(a00, w0, xb0); ffma2(a01, w1, xb0);                     \
            ffma2(a10, w0, xb1); ffma2(a11, w1, xb1);                     \
        }                                                                 \
    }

__device__ __forceinline__ u64 ln_pair(u64 y, u64 gamma, float scale) {
    float a = lo32(y), b = hi32(y);
    float s = a + b;
#pragma unroll
    for (int o = 16; o > 0; o >>= 1) s += __shfl_xor_sync(0xffffffffu, s, o);
    float mean = s * (1.f / 64.f);
    float da = a - mean, db = b - mean;
    float q = da * da + db * db;
#pragma unroll
    for (int o = 16; o > 0; o >>= 1) q += __shfl_xor_sync(0xffffffffu, q, o);
    float inv = rsqrtf(q * (1.f / 64.f) + 1e-5f) * scale;
    return pack2(da * inv * lo32(gamma), db * inv * hi32(gamma));
}

__global__ __launch_bounds__(256, 1) void k_heads(
    const float* __restrict__ Wlq, const float* __restrict__ blq,
    const float* __restrict__ Wlk, const float* __restrict__ blk,
    const float* __restrict__ Wlv, const float* __restrict__ blv,
    const float* __restrict__ lnc, const float* __restrict__ lnd,
    const float* __restrict__ temp_p) {
    extern __shared__ u64 smu[];
    int tid = threadIdx.x;
    int w = tid >> 5, lane = tid & 31;
    int bb = blockIdx.x >> 4, h = blockIdx.x & 15;
    int e0 = w, e1 = w + 8;

    // stage 3 weight matrices as u64 pairs, row stride 33
    for (int idx = tid; idx < 3 * 2048; idx += 256) {
        int m = idx >> 11, r = idx & 2047;
        int j = r >> 5, s = r & 31;
        const float* Wm = (m == 0) ? Wlq : (m == 1) ? Wlk : Wlv;
        cp8(smem_u32p(&smu[m * 2112 + j * 33 + s]), &Wm[j * 64 + 2 * s]);
    }
    cp_commit();

    // register state: one pair per lane per row
    size_t base0 = (size_t)((bb * 16 + e0) * 16 + h) * 64 + 2 * lane;
    size_t base1 = (size_t)((bb * 16 + e1) * 16 + h) * 64 + 2 * lane;
    u64 q0 = *(const u64*)&g_q[base0], q1 = *(const u64*)&g_q[base1];
    u64 k0 = *(const u64*)&g_k[base0], k1 = *(const u64*)&g_k[base1];
    u64 v0 = *(const u64*)&g_v[base0], v1 = *(const u64*)&g_v[base1];
    u64 blq_p = *(const u64*)&blq[2 * lane];
    u64 blk_p = *(const u64*)&blk[2 * lane];
    u64 blv_p = *(const u64*)&blv[2 * lane];
    u64 lnc_p = *(const u64*)&lnc[2 * lane];
    u64 lnd_p = *(const u64*)&lnd[2 * lane];
    float temp0 = temp_p[0];
    u64 ap0 = 0, ap1 = 0;
    cp_wait0();
    __syncthreads();

    const u64* wq = smu + WQ_OFF;
    const u64* wk = smu + WK_OFF;
    const u64* wv = smu + WV_OFF;

    for (int it = 0; it < 3; it++) {
        u64* ksb = smu + KSB_OFF + (it & 1) * 528;
        u64* vlb = smu + VLB_OFF + (it & 1) * 528;

        // ---- k recurrence + LN publish ----
        u64 a00, a01, a10, a11;
        GEMV2(wk, k0, k1, a00, a01, a10, a11);
        k0 = pack2(lo32(a00) + hi32(a00) + lo32(blk_p),
                   lo32(a01) + hi32(a01) + hi32(blk_p));
        k1 = pack2(lo32(a10) + hi32(a10) + lo32(blk_p),
                   lo32(a11) + hi32(a11) + hi32(blk_p));
        ksb[e0 * 33 + lane] = ln_pair(k0, lnd_p, 1.0f);
        ksb[e1 * 33 + lane] = ln_pair(k1, lnd_p, 1.0f);

        // ---- v recurrence publish ----
        GEMV2(wv, v0, v1, a00, a01, a10, a11);
        v0 = pack2(lo32(a00) + hi32(a00) + lo32(blv_p),
                   lo32(a01) + hi32(a01) + hi32(blv_p));
        v1 = pack2(lo32(a10) + hi32(a10) + lo32(blv_p),
                   lo32(a11) + hi32(a11) + hi32(blv_p));
        vlb[e0 * 33 + lane] = v0;
        vlb[e1 * 33 + lane] = v1;

        // ---- q projection + LN (registers only) ----
        GEMV2(wq, q0, q1, a00, a01, a10, a11);
        u64 ql0 = pack2(lo32(a00) + hi32(a00) + lo32(blq_p),
                        lo32(a01) + hi32(a01) + hi32(blq_p));
        u64 ql1 = pack2(lo32(a10) + hi32(a10) + lo32(blq_p),
                        lo32(a11) + hi32(a11) + hi32(blq_p));
        float t_it = temp0 + 0.005f * (float)it;
        float tsc = ((t_it != 1.0f) && (t_it > 0.f)) ? rsqrtf(t_it) : 1.0f;
        float sc = tsc * SM_SCALE;
        u64 qs0 = ln_pair(ql0, lnc_p, sc);
        u64 qs1 = ln_pair(ql1, lnc_p, sc);

        __syncthreads();   // k/v of this iteration published (all warps)

        // ---- logits + softmax + AV, per row ----
        int f = lane & 15, dh = lane >> 4;
        u64 ai[2];
#pragma unroll
        for (int r = 0; r < 2; r++) {
            u64 qs = r ? qs1 : qs0;
            u64 acc = 0;
#pragma unroll 4
            for (int s = 0; s < 16; s++) {
                int pi = dh * 16 + s;
                u64 qb = shfl64(qs, pi);
                ffma2(acc, qb, ksb[f * 33 + pi]);
            }
            float lg = lo32(acc) + hi32(acc);
            lg += __shfl_xor_sync(0xffffffffu, lg, 16);
            float mx = lg;
#pragma unroll
            for (int o = 8; o > 0; o >>= 1)
                mx = fmaxf(mx, __shfl_xor_sync(0xffffffffu, mx, o, 16));
            float ex = __expf(lg - mx);
            float sm = ex;
#pragma unroll
            for (int o = 8; o > 0; o >>= 1)
                sm += __shfl_xor_sync(0xffffffffu, sm, o, 16);
            float pr = __fdividef(ex, sm);
            u64 av = 0;
#pragma unroll 4
            for (int s = 0; s < 16; s++) {
                float pv = __shfl_sync(0xffffffffu, pr, s);
                ffma2(av, pack2(pv, pv), vlb[s * 33 + lane]);
            }
            ai[r] = av;
        }

        // ---- bookkeeping ----
        if (it == 0) { ap0 = ai[0]; ap1 = ai[1]; }
        if (it >= 1) {
            float* dst = (it == 1) ? g_ai1 : g_ai2;
            *(u64*)&dst[base0] = ai[0];
            *(u64*)&dst[base1] = ai[1];
        }
        if (it == 1) {
            float ds = fabsf(lo32(ai[0]) - lo32(ap0)) + fabsf(hi32(ai[0]) - hi32(ap0))
                     + fabsf(lo32(ai[1]) - lo32(ap1)) + fabsf(hi32(ai[1]) - hi32(ap1));
#pragma unroll
            for (int o = 16; o > 0; o >>= 1)
                ds += __shfl_xor_sync(0xffffffffu, ds, o);
            if (lane == 0) atomicAdd(&g_diffsum, ds);
        }
        q0 = fadd2(q0, ai[0]);
        q1 = fadd2(q1, ai[1]);
    }
}

// ======================= K4: select ai, Wo proj, red.v4 into out ==========
__global__ __launch_bounds__(128) void k_out(
    const float* __restrict__ Wo, const float* __restrict__ thrp,
    const float* __restrict__ facp, float* __restrict__ out) {
    extern __shared__ float sh[];
    float* sA = sh;
    float* sW = sh + 64 * TK;
    float diff1 = g_diffsum * (1.0f / 8388608.0f);  // mean over B*H*T*hd
    const float* A = (diff1 < thrp[0] + facp[0] * diff1) ? g_ai1 : g_ai2;
    int j0 = blockIdx.x * 128;
    int kb = blockIdx.y * TK;
    u64 acc[64] = {};
    stage_tile(A, Wo, j0, kb, sA, sW);
    cp_wait0();
    __syncthreads();
    int tid = threadIdx.x, rg = tid & 7, cg = tid >> 3;
    compute_tile(sA, sW, acc, rg, cg);
    int c0 = j0 + cg * 8;
#pragma unroll
    for (int i = 0; i < 8; i++) {
        int row = rg * 8 + i;
        int b = row >> 4, t = row & 15;
        float v[8];
#pragma unroll
        for (int j = 0; j < 8; j++) {
            float2 f = *(float2*)&acc[i * 8 + j];
            v[j] = f.x + f.y;
        }
        float* p = &out[((size_t)(b * Tn + t)) * Dn + c0];
        red4(p, v[0], v[1], v[2], v[3]);
        red4(p + 4, v[4], v[5], v[6], v[7]);
    }
}

// ======================= launch ===========================================
extern "C" void kernel_launch(void* const* d_in, const int* in_sizes, int n_in,
                              void* d_out, int out_size) {
    (void)in_sizes; (void)n_in; (void)out_size;
    const float* x    = (const float*)d_in[0];
    const float* Wq   = (const float*)d_in[1];
    const float* bq   = (const float*)d_in[2];
    const float* Wk   = (const float*)d_in[3];
    const float* Wv   = (const float*)d_in[4];
    const float* bv   = (const float*)d_in[5];
    const float* Wo   = (const float*)d_in[6];
    const float* bo   = (const float*)d_in[7];
    const float* lna  = (const float*)d_in[8];
    const float* lnc  = (const float*)d_in[9];
    const float* lnd  = (const float*)d_in[10];
    const float* Wlq  = (const float*)d_in[11];
    const float* blq  = (const float*)d_in[12];
    const float* Wlk  = (const float*)d_in[13];
    const float* blk  = (const float*)d_in[14];
    const float* Wlv  = (const float*)d_in[15];
    const float* blv  = (const float*)d_in[16];
    const float* temp = (const float*)d_in[17];
    const float* thr  = (const float*)d_in[18];
    const float* fac  = (const float*)d_in[19];
    float* out = (float*)d_out;

    static cudaStream_t s2 = nullptr;
    static cudaEvent_t evF = nullptr, evJ = nullptr;
    static bool attrs_set = false;
    if (s2 == nullptr) {
        cudaStreamCreateWithFlags(&s2, cudaStreamNonBlocking);
        cudaEventCreateWithFlags(&evF, cudaEventDisableTiming);
        cudaEventCreateWithFlags(&evJ, cudaEventDisableTiming);
    }
    if (!attrs_set) {
        cudaFuncSetAttribute(k_qkv,   cudaFuncAttributeMaxDynamicSharedMemorySize, GEMM_SMEM);
        cudaFuncSetAttribute(k_out,   cudaFuncAttributeMaxDynamicSharedMemorySize, GEMM_SMEM);
        cudaFuncSetAttribute(k_heads, cudaFuncAttributeMaxDynamicSharedMemorySize, KHEADS_SMEM);
        attrs_set = true;
    }

    // fork: bo-fill runs concurrently on s2
    cudaEventRecord(evF, 0);
    cudaStreamWaitEvent(s2, evF, 0);
    k_fill<<<1024, 256, 0, s2>>>(bo, out);

    // main chain on stream 0
    k_ln<<<128, 256>>>(x, lna, bq, bv);
    k_qkv<<<dim3(8, 16, 3), 128, GEMM_SMEM>>>(Wq, Wk, Wv);
    k_heads<<<64, 256, KHEADS_SMEM>>>(Wlq, blq, Wlk, blk, Wlv, blv, lnc, lnd, temp);

    // join fill before final projection (which red.adds into out)
    cudaEventRecord(evJ, s2);
    cudaStreamWaitEvent(0, evJ, 0);
    k_out<<<dim3(8, 16), 128, GEMM_SMEM>>>(Wo, thr, fac, out);
}

// round 10
// speedup vs baseline: 1.5260x; 1.5260x over previous
#include <cuda_runtime.h>
#include <math.h>

#define Bn 4
#define Tn 2048
#define Dn 1024
#define Hn 16
#define HDn 64
#define En 16
#define Rn 64                     // Bn*En active rows
#define QK_SCALE 0.35355339059327373f   // hd^-0.25
#define SM_SCALE 0.125f                 // 1/sqrt(hd)

typedef unsigned long long u64;

// ---------------- scratch (static device globals; no allocation) ----------
__device__ float g_xn[Rn * Dn];
__device__ float g_q[Rn * Dn];     // qcur, flat [1024][64] as (b,e,h)
__device__ float g_k[Rn * Dn];     // kcur
__device__ float g_v[Rn * Dn];     // vcur (= vl of current iter)
__device__ float g_qs[Rn * Dn];    // LN'd ql
__device__ float g_ks[Rn * Dn];    // LN'd kl
__device__ float g_ai1[Rn * Dn];
__device__ float g_ai2[Rn * Dn];   // also scratch for ai_0
__device__ float g_diffsum;

// ---------------- helpers -------------------------------------------------
__device__ __forceinline__ float warpReduceSum(float v) {
#pragma unroll
    for (int o = 16; o > 0; o >>= 1) v += __shfl_xor_sync(0xffffffffu, v, o);
    return v;
}

__device__ __forceinline__ float blockReduce256(float v, float* sh) {
    __syncthreads();
    v = warpReduceSum(v);
    int wid = threadIdx.x >> 5;
    if ((threadIdx.x & 31) == 0) sh[wid] = v;
    __syncthreads();
    if (threadIdx.x < 32) {
        float t = (threadIdx.x < 8) ? sh[threadIdx.x] : 0.f;
        t = warpReduceSum(t);
        if (threadIdx.x == 0) sh[0] = t;
    }
    __syncthreads();
    return sh[0];
}

// packed fp32x2 FMA (sm_100+)
__device__ __forceinline__ void ffma2(u64& d, u64 a, u64 b) {
    asm("fma.rn.f32x2 %0, %1, %2, %0;" : "+l"(d) : "l"(a), "l"(b));
}
__device__ __forceinline__ u64 fadd2(u64 a, u64 b) {
    u64 r;
    asm("add.rn.f32x2 %0, %1, %2;" : "=l"(r) : "l"(a), "l"(b));
    return r;
}
__device__ __forceinline__ u64 pack2(float a, float b) {
    u64 r;
    asm("mov.b64 %0, {%1, %2};" : "=l"(r) : "f"(a), "f"(b));
    return r;
}
__device__ __forceinline__ float lo32(u64 v) { return ((float2*)&v)->x; }
__device__ __forceinline__ float hi32(u64 v) { return ((float2*)&v)->y; }

__device__ __forceinline__ unsigned smem_u32p(const void* p) {
    return (unsigned)__cvta_generic_to_shared(p);
}
__device__ __forceinline__ void cp16(unsigned dst, const void* src) {
    asm volatile("cp.async.cg.shared.global [%0], [%1], 16;" :: "r"(dst), "l"(src));
}
__device__ __forceinline__ void cp8(unsigned dst, const void* src) {
    asm volatile("cp.async.ca.shared.global [%0], [%1], 8;" :: "r"(dst), "l"(src));
}
__device__ __forceinline__ void cp_commit() {
    asm volatile("cp.async.commit_group;");
}
__device__ __forceinline__ void cp_wait0() {
    asm volatile("cp.async.wait_group 0;");
}
// vector float atomic add (sm_90+)
__device__ __forceinline__ void red4(float* p, float a, float b, float c, float d) {
    asm volatile("red.global.add.v4.f32 [%0], {%1,%2,%3,%4};"
                 :: "l"(p), "f"(a), "f"(b), "f"(c), "f"(d) : "memory");
}

// full-warp LN over 64 elements held as one f32x2 pair per lane
__device__ __forceinline__ u64 ln_pair(u64 y, u64 gamma, float scale) {
    float a = lo32(y), b = hi32(y);
    float s = a + b;
#pragma unroll
    for (int o = 16; o > 0; o >>= 1) s += __shfl_xor_sync(0xffffffffu, s, o);
    float mean = s * (1.f / 64.f);
    float da = a - mean, db = b - mean;
    float q = da * da + db * db;
#pragma unroll
    for (int o = 16; o > 0; o >>= 1) q += __shfl_xor_sync(0xffffffffu, q, o);
    float inv = rsqrtf(q * (1.f / 64.f) + 1e-5f) * scale;
    return pack2(da * inv * lo32(gamma), db * inv * hi32(gamma));
}

// ======================= K1a: LN(64 rows) + accumulator inits =============
__global__ __launch_bounds__(256) void k_ln(
    const float* __restrict__ x, const float* __restrict__ lna,
    const float* __restrict__ bq, const float* __restrict__ bv) {
    if (blockIdx.x < Rn) {
        __shared__ float sh[8];
        if (blockIdx.x == 0 && threadIdx.x == 0) g_diffsum = 0.f;
        int r = blockIdx.x;
        int b = r >> 4, t = r & 15;
        const float* xr = x + ((size_t)(b * Tn + t)) * Dn;
        int tid = threadIdx.x;
        float v[4];
        float s = 0.f;
#pragma unroll
        for (int i = 0; i < 4; i++) { v[i] = xr[tid + i * 256]; s += v[i]; }
        s = blockReduce256(s, sh);
        float mean = s * (1.f / 1024.f);
        float sq = 0.f;
#pragma unroll
        for (int i = 0; i < 4; i++) { float d = v[i] - mean; sq += d * d; }
        sq = blockReduce256(sq, sh);
        float inv = rsqrtf(sq * (1.f / 1024.f) + 1e-5f);
#pragma unroll
        for (int i = 0; i < 4; i++) {
            int j = tid + i * 256;
            g_xn[r * Dn + j] = (v[i] - mean) * inv * lna[j];
        }
    } else {
        int r = blockIdx.x - Rn;
        int tid = threadIdx.x;
#pragma unroll
        for (int i = 0; i < 4; i++) {
            int j = tid + i * 256;
            g_q[r * Dn + j] = bq[j] * QK_SCALE;
            g_k[r * Dn + j] = 0.f;
            g_v[r * Dn + j] = bv[j];
        }
    }
}

// ======================= K1b: bo fill of whole output (side stream) =======
__global__ __launch_bounds__(256) void k_fill(
    const float* __restrict__ bo, float* __restrict__ out) {
    const float4* bo4 = (const float4*)bo;
    float4* o4 = (float4*)out;
    size_t total = (size_t)Bn * Tn * Dn / 4;
    size_t start = (size_t)blockIdx.x * 256 + threadIdx.x;
    size_t stride = (size_t)gridDim.x * 256;
    float4 v = bo4[start & 255];
    for (size_t i = start; i < total; i += stride) o4[i] = v;
}

// ======================= 64x128 FFMA2 GEMM tile core ======================
#define TK 64

__device__ __forceinline__ void stage_tile(
    const float* __restrict__ A, const float* __restrict__ W,
    int j0, int kb, float* sA, float* sW) {
    int tid = threadIdx.x;
#pragma unroll
    for (int c = tid; c < 64 * TK / 2; c += 128) {
        int r = c >> 5;
        int kf = (c & 31) * 2;
        int rg = r >> 3;
        int swz = ((rg & 3) * 8) | ((rg >> 2) * 2);
        cp8(smem_u32p(&sA[r * TK + (kf ^ swz)]),
            &A[(size_t)r * Dn + kb + kf]);
    }
#pragma unroll
    for (int c = tid; c < 128 * TK / 4; c += 128) {
        int r = c >> 4;
        int kf = (c & 15) * 4;
        cp16(smem_u32p(&sW[r * TK + kf]),
             &W[(size_t)(j0 + r) * Dn + kb + kf]);
    }
    cp_commit();
}

__device__ __forceinline__ void compute_tile(
    const float* sA, const float* sW, u64* acc, int rg, int cg) {
    int swz = ((rg & 3) * 8) | ((rg >> 2) * 2);
    const float* aBase = sA + rg * 8 * TK;
    const float* wBase = sW + cg * 8 * TK;
#pragma unroll 4
    for (int kk = 0; kk < TK; kk += 2) {
        int ka = kk ^ swz;
        u64 av[8], wv[8];
#pragma unroll
        for (int i = 0; i < 8; i++)
            av[i] = *(const u64*)&aBase[i * TK + ka];
#pragma unroll
        for (int j = 0; j < 8; j++)
            wv[j] = *(const u64*)&wBase[j * TK + kk];
#pragma unroll
        for (int i = 0; i < 8; i++)
#pragma unroll
            for (int j = 0; j < 8; j++) ffma2(acc[i * 8 + j], av[i], wv[j]);
    }
}
#define GEMM_SMEM ((64 + 128) * TK * 4)   // 49152 bytes

// ======================= K2: q,k,v GEMMs (k-split 16, red.v4) =============
__global__ __launch_bounds__(128) void k_qkv(
    const float* __restrict__ Wq, const float* __restrict__ Wk,
    const float* __restrict__ Wv) {
    extern __shared__ float sh[];
    float* sA = sh;
    float* sW = sh + 64 * TK;
    int m = blockIdx.z;
    const float* W = (m == 0) ? Wq : (m == 1) ? Wk : Wv;
    float* dst = (m == 0) ? g_q : (m == 1) ? g_k : g_v;
    float scale = (m == 2) ? 1.0f : QK_SCALE;
    int j0 = blockIdx.x * 128;
    int kb = blockIdx.y * TK;
    u64 acc[64] = {};
    stage_tile(g_xn, W, j0, kb, sA, sW);
    cp_wait0();
    __syncthreads();
    int tid = threadIdx.x, rg = tid & 7, cg = tid >> 3;
    compute_tile(sA, sW, acc, rg, cg);
    int c0 = j0 + cg * 8;
#pragma unroll
    for (int i = 0; i < 8; i++) {
        int row = rg * 8 + i;
        float v[8];
#pragma unroll
        for (int j = 0; j < 8; j++) {
            float2 f = *(float2*)&acc[i * 8 + j];
            v[j] = (f.x + f.y) * scale;
        }
        float* p = &dst[(size_t)row * Dn + c0];
        red4(p, v[0], v[1], v[2], v[3]);
        red4(p + 4, v[4], v[5], v[6], v[7]);
    }
}

// ======================= K3a (x3): wide projection kernel =================
// grid (32, 3): blockIdx.y selects matrix (0=q,1=k,2=v). Each block handles
// 32 of the 1024 flat (b,e,h) rows: y_row = x_row @ W^T + b, then LN for
// q (lnc, tsc*SM_SCALE) and k (lnd). Warp owns 4 rows; W-loads amortized.
__global__ __launch_bounds__(256, 1) void k_A(
    const float* __restrict__ Wlq, const float* __restrict__ blq,
    const float* __restrict__ Wlk, const float* __restrict__ blk,
    const float* __restrict__ Wlv, const float* __restrict__ blv,
    const float* __restrict__ lnc, const float* __restrict__ lnd,
    const float* __restrict__ temp_p, int it) {
    __shared__ u64 sw[64 * 33];
    __shared__ u64 sx[32 * 33];
    int tid = threadIdx.x, lane = tid & 31, w = tid >> 5;
    int m = blockIdx.y;
    int r0 = blockIdx.x * 32;
    const float* Wm = (m == 0) ? Wlq : (m == 1) ? Wlk : Wlv;
    const float* blp = (m == 0) ? blq : (m == 1) ? blk : blv;
    const float* X = (m == 0) ? g_q : (m == 1) ? g_k : g_v;
    for (int i = tid; i < 2048; i += 256) {
        int j = i >> 5, s = i & 31;
        cp8(smem_u32p(&sw[j * 33 + s]), &Wm[j * 64 + 2 * s]);
    }
    for (int i = tid; i < 1024; i += 256) {
        int r = i >> 5, s = i & 31;
        cp8(smem_u32p(&sx[r * 33 + s]), &X[(size_t)(r0 + r) * 64 + 2 * s]);
    }
    cp_commit();
    u64 bl_p = *(const u64*)&blp[2 * lane];
    u64 ln_p;
    float sc;
    if (m == 0) {
        ln_p = *(const u64*)&lnc[2 * lane];
        float t_it = temp_p[0] + 0.005f * (float)it;
        float tsc = ((t_it != 1.0f) && (t_it > 0.f)) ? rsqrtf(t_it) : 1.0f;
        sc = tsc * SM_SCALE;
    } else {
        ln_p = *(const u64*)&lnd[2 * lane];
        sc = 1.0f;
    }
    cp_wait0();
    __syncthreads();

    // 4 rows per warp, fused inner loop (W pair reused across rows)
    u64 acc[4][2] = {};
    const u64* w0p = &sw[(2 * lane) * 33];
    const u64* w1p = w0p + 33;
#pragma unroll 4
    for (int s = 0; s < 32; s++) {
        u64 w0 = w0p[s], w1 = w1p[s];
#pragma unroll
        for (int rr = 0; rr < 4; rr++) {
            u64 xb = sx[(w + rr * 8) * 33 + s];
            ffma2(acc[rr][0], xb, w0);
            ffma2(acc[rr][1], xb, w1);
        }
    }
#pragma unroll
    for (int rr = 0; rr < 4; rr++) {
        int r = w + rr * 8;
        u64 pair = pack2(lo32(acc[rr][0]) + hi32(acc[rr][0]) + lo32(bl_p),
                         lo32(acc[rr][1]) + hi32(acc[rr][1]) + hi32(bl_p));
        size_t g = (size_t)(r0 + r) * 64 + 2 * lane;
        if (m == 0) {
            *(u64*)&g_qs[g] = ln_pair(pair, ln_p, sc);
        } else if (m == 1) {
            *(u64*)&g_k[g] = pair;                       // kcur for next iter
            *(u64*)&g_ks[g] = ln_pair(pair, ln_p, 1.0f); // LN'd for logits
        } else {
            *(u64*)&g_v[g] = pair;                       // vl (= vcur next)
        }
    }
}

// ======================= K3b (x3): per-head attention step ================
// 64 blocks (one per (b,h)), 256 threads = 8 warps; warp w owns e-rows
// {w, w+8}. Logits/softmax/AV from smem (no shuffle GEMVs); qcur updated
// in global; diff handled at it==1 using g_ai2 as ai_0 scratch.
__global__ __launch_bounds__(256, 1) void k_B(int it) {
    __shared__ u64 sq[16 * 33], sk[16 * 33], sv[16 * 33];
    __shared__ float red[8];
    int tid = threadIdx.x, lane = tid & 31, w = tid >> 5;
    int bb = blockIdx.x >> 4, h = blockIdx.x & 15;
    for (int i = tid; i < 512; i += 256) {
        int e = i >> 5, s = i & 31;
        size_t g = ((size_t)((bb * 16 + e) * 16 + h)) * 64 + 2 * s;
        cp8(smem_u32p(&sq[e * 33 + s]), &g_qs[g]);
        cp8(smem_u32p(&sk[e * 33 + s]), &g_ks[g]);
        cp8(smem_u32p(&sv[e * 33 + s]), &g_v[g]);
    }
    cp_commit();
    cp_wait0();
    __syncthreads();
    int e0 = w, e1 = w + 8;
    int f = lane & 15, dh = lane >> 4;
    // logits[e][f] split across dh halves of the d-range
    u64 acc0 = 0, acc1 = 0;
#pragma unroll
    for (int s = 0; s < 16; s++) {
        int p = dh * 16 + s;
        u64 kv = sk[f * 33 + p];
        ffma2(acc0, sq[e0 * 33 + p], kv);
        ffma2(acc1, sq[e1 * 33 + p], kv);
    }
    float lg0 = lo32(acc0) + hi32(acc0);
    float lg1 = lo32(acc1) + hi32(acc1);
    lg0 += __shfl_xor_sync(0xffffffffu, lg0, 16);
    lg1 += __shfl_xor_sync(0xffffffffu, lg1, 16);
    float mx0 = lg0, mx1 = lg1;
#pragma unroll
    for (int o = 8; o > 0; o >>= 1) {
        mx0 = fmaxf(mx0, __shfl_xor_sync(0xffffffffu, mx0, o, 16));
        mx1 = fmaxf(mx1, __shfl_xor_sync(0xffffffffu, mx1, o, 16));
    }
    float ex0 = __expf(lg0 - mx0), ex1 = __expf(lg1 - mx1);
    float s0 = ex0, s1 = ex1;
#pragma unroll
    for (int o = 8; o > 0; o >>= 1) {
        s0 += __shfl_xor_sync(0xffffffffu, s0, o, 16);
        s1 += __shfl_xor_sync(0xffffffffu, s1, o, 16);
    }
    float pr0 = __fdividef(ex0, s0), pr1 = __fdividef(ex1, s1);
    // ai = softmax @ vl ; lane holds cols (2*lane, 2*lane+1)
    u64 av0 = 0, av1 = 0;
#pragma unroll
    for (int s = 0; s < 16; s++) {
        float p0 = __shfl_sync(0xffffffffu, pr0, s);
        float p1 = __shfl_sync(0xffffffffu, pr1, s);
        u64 vv = sv[s * 33 + lane];
        ffma2(av0, pack2(p0, p0), vv);
        ffma2(av1, pack2(p1, p1), vv);
    }
    size_t g0 = ((size_t)((bb * 16 + e0) * 16 + h)) * 64 + 2 * lane;
    size_t g1 = ((size_t)((bb * 16 + e1) * 16 + h)) * 64 + 2 * lane;
    if (it < 2) {   // qcur += ai (not needed after last iteration)
        *(u64*)&g_q[g0] = fadd2(*(const u64*)&g_q[g0], av0);
        *(u64*)&g_q[g1] = fadd2(*(const u64*)&g_q[g1], av1);
    }
    if (it == 0) {                 // scratch ai_0 for the diff
        *(u64*)&g_ai2[g0] = av0;
        *(u64*)&g_ai2[g1] = av1;
    } else if (it == 1) {
        u64 p0v = *(const u64*)&g_ai2[g0];
        u64 p1v = *(const u64*)&g_ai2[g1];
        float ds = fabsf(lo32(av0) - lo32(p0v)) + fabsf(hi32(av0) - hi32(p0v))
                 + fabsf(lo32(av1) - lo32(p1v)) + fabsf(hi32(av1) - hi32(p1v));
        *(u64*)&g_ai1[g0] = av0;
        *(u64*)&g_ai1[g1] = av1;
        float tot = blockReduce256(ds, red);
        if (tid == 0) atomicAdd(&g_diffsum, tot);
    } else {                       // it == 2 overwrites the scratch
        *(u64*)&g_ai2[g0] = av0;
        *(u64*)&g_ai2[g1] = av1;
    }
}

// ======================= K4: select ai, Wo proj, red.v4 into out ==========
__global__ __launch_bounds__(128) void k_out(
    const float* __restrict__ Wo, const float* __restrict__ thrp,
    const float* __restrict__ facp, float* __restrict__ out) {
    extern __shared__ float sh[];
    float* sA = sh;
    float* sW = sh + 64 * TK;
    float diff1 = g_diffsum * (1.0f / 8388608.0f);  // mean over B*H*T*hd
    const float* A = (diff1 < thrp[0] + facp[0] * diff1) ? g_ai1 : g_ai2;
    int j0 = blockIdx.x * 128;
    int kb = blockIdx.y * TK;
    u64 acc[64] = {};
    stage_tile(A, Wo, j0, kb, sA, sW);
    cp_wait0();
    __syncthreads();
    int tid = threadIdx.x, rg = tid & 7, cg = tid >> 3;
    compute_tile(sA, sW, acc, rg, cg);
    int c0 = j0 + cg * 8;
#pragma unroll
    for (int i = 0; i < 8; i++) {
        int row = rg * 8 + i;
        int b = row >> 4, t = row & 15;
        float v[8];
#pragma unroll
        for (int j = 0; j < 8; j++) {
            float2 f = *(float2*)&acc[i * 8 + j];
            v[j] = f.x + f.y;
        }
        float* p = &out[((size_t)(b * Tn + t)) * Dn + c0];
        red4(p, v[0], v[1], v[2], v[3]);
        red4(p + 4, v[4], v[5], v[6], v[7]);
    }
}

// ======================= launch ===========================================
extern "C" void kernel_launch(void* const* d_in, const int* in_sizes, int n_in,
                              void* d_out, int out_size) {
    (void)in_sizes; (void)n_in; (void)out_size;
    const float* x    = (const float*)d_in[0];
    const float* Wq   = (const float*)d_in[1];
    const float* bq   = (const float*)d_in[2];
    const float* Wk   = (const float*)d_in[3];
    const float* Wv   = (const float*)d_in[4];
    const float* bv   = (const float*)d_in[5];
    const float* Wo   = (const float*)d_in[6];
    const float* bo   = (const float*)d_in[7];
    const float* lna  = (const float*)d_in[8];
    const float* lnc  = (const float*)d_in[9];
    const float* lnd  = (const float*)d_in[10];
    const float* Wlq  = (const float*)d_in[11];
    const float* blq  = (const float*)d_in[12];
    const float* Wlk  = (const float*)d_in[13];
    const float* blk  = (const float*)d_in[14];
    const float* Wlv  = (const float*)d_in[15];
    const float* blv  = (const float*)d_in[16];
    const float* temp = (const float*)d_in[17];
    const float* thr  = (const float*)d_in[18];
    const float* fac  = (const float*)d_in[19];
    float* out = (float*)d_out;

    static cudaStream_t s2 = nullptr;
    static cudaEvent_t evF = nullptr, evJ = nullptr;
    static bool attrs_set = false;
    if (s2 == nullptr) {
        cudaStreamCreateWithFlags(&s2, cudaStreamNonBlocking);
        cudaEventCreateWithFlags(&evF, cudaEventDisableTiming);
        cudaEventCreateWithFlags(&evJ, cudaEventDisableTiming);
    }
    if (!attrs_set) {
        cudaFuncSetAttribute(k_qkv, cudaFuncAttributeMaxDynamicSharedMemorySize, GEMM_SMEM);
        cudaFuncSetAttribute(k_out, cudaFuncAttributeMaxDynamicSharedMemorySize, GEMM_SMEM);
        attrs_set = true;
    }

    // fork: bo-fill runs concurrently on s2
    cudaEventRecord(evF, 0);
    cudaStreamWaitEvent(s2, evF, 0);
    k_fill<<<1024, 256, 0, s2>>>(bo, out);

    // main chain on stream 0
    k_ln<<<128, 256>>>(x, lna, bq, bv);
    k_qkv<<<dim3(8, 16, 3), 128, GEMM_SMEM>>>(Wq, Wk, Wv);
    for (int it = 0; it < 3; it++) {
        k_A<<<dim3(32, 3), 256>>>(Wlq, blq, Wlk, blk, Wlv, blv, lnc, lnd, temp, it);
        k_B<<<64, 256>>>(it);
    }

    // join fill before final projection (which red.adds into out)
    cudaEventRecord(evJ, s2);
    cudaStreamWaitEvent(0, evJ, 0);
    k_out<<<dim3(8, 16), 128, GEMM_SMEM>>>(Wo, thr, fac, out);
}

// round 11
// speedup vs baseline: 1.6168x; 1.0595x over previous
#include <cuda_runtime.h>
#include <math.h>

#define Bn 4
#define Tn 2048
#define Dn 1024
#define Hn 16
#define HDn 64
#define En 16
#define Rn 64                     // Bn*En active rows
#define QK_SCALE 0.35355339059327373f   // hd^-0.25
#define SM_SCALE 0.125f                 // 1/sqrt(hd)

typedef unsigned long long u64;

// ---------------- scratch (static device globals; no allocation) ----------
__device__ float g_xn[Rn * Dn];
__device__ float g_q[Rn * Dn];     // q init (post-bias/scale), flat [1024][64]
__device__ float g_k[Rn * Dn];     // k init
__device__ float g_v[Rn * Dn];     // v init
__device__ float g_ks[3 * 65536];  // LN'd kl per iteration
__device__ float g_vl[3 * 65536];  // vl per iteration
__device__ float g_ai1[Rn * Dn];
__device__ float g_ai2[Rn * Dn];
__device__ float g_diffsum;

// ---------------- helpers -------------------------------------------------
__device__ __forceinline__ float warpReduceSum(float v) {
#pragma unroll
    for (int o = 16; o > 0; o >>= 1) v += __shfl_xor_sync(0xffffffffu, v, o);
    return v;
}

__device__ __forceinline__ float blockReduce256(float v, float* sh) {
    __syncthreads();
    v = warpReduceSum(v);
    int wid = threadIdx.x >> 5;
    if ((threadIdx.x & 31) == 0) sh[wid] = v;
    __syncthreads();
    if (threadIdx.x < 32) {
        float t = (threadIdx.x < 8) ? sh[threadIdx.x] : 0.f;
        t = warpReduceSum(t);
        if (threadIdx.x == 0) sh[0] = t;
    }
    __syncthreads();
    return sh[0];
}

// packed fp32x2 FMA (sm_100+)
__device__ __forceinline__ void ffma2(u64& d, u64 a, u64 b) {
    asm("fma.rn.f32x2 %0, %1, %2, %0;" : "+l"(d) : "l"(a), "l"(b));
}
__device__ __forceinline__ u64 fadd2(u64 a, u64 b) {
    u64 r;
    asm("add.rn.f32x2 %0, %1, %2;" : "=l"(r) : "l"(a), "l"(b));
    return r;
}
__device__ __forceinline__ u64 pack2(float a, float b) {
    u64 r;
    asm("mov.b64 %0, {%1, %2};" : "=l"(r) : "f"(a), "f"(b));
    return r;
}
__device__ __forceinline__ float lo32(u64 v) { return ((float2*)&v)->x; }
__device__ __forceinline__ float hi32(u64 v) { return ((float2*)&v)->y; }

__device__ __forceinline__ unsigned smem_u32p(const void* p) {
    return (unsigned)__cvta_generic_to_shared(p);
}
__device__ __forceinline__ void cp16(unsigned dst, const void* src) {
    asm volatile("cp.async.cg.shared.global [%0], [%1], 16;" :: "r"(dst), "l"(src));
}
__device__ __forceinline__ void cp8(unsigned dst, const void* src) {
    asm volatile("cp.async.ca.shared.global [%0], [%1], 8;" :: "r"(dst), "l"(src));
}
__device__ __forceinline__ void cp_commit() {
    asm volatile("cp.async.commit_group;");
}
__device__ __forceinline__ void cp_wait0() {
    asm volatile("cp.async.wait_group 0;");
}
// vector float atomic add (sm_90+)
__device__ __forceinline__ void red4(float* p, float a, float b, float c, float d) {
    asm volatile("red.global.add.v4.f32 [%0], {%1,%2,%3,%4};"
                 :: "l"(p), "f"(a), "f"(b), "f"(c), "f"(d) : "memory");
}

// full-warp LN over 64 elements held as one f32x2 pair per lane
__device__ __forceinline__ u64 ln_pair(u64 y, u64 gamma, float scale) {
    float a = lo32(y), b = hi32(y);
    float s = a + b;
#pragma unroll
    for (int o = 16; o > 0; o >>= 1) s += __shfl_xor_sync(0xffffffffu, s, o);
    float mean = s * (1.f / 64.f);
    float da = a - mean, db = b - mean;
    float q = da * da + db * db;
#pragma unroll
    for (int o = 16; o > 0; o >>= 1) q += __shfl_xor_sync(0xffffffffu, q, o);
    float inv = rsqrtf(q * (1.f / 64.f) + 1e-5f) * scale;
    return pack2(da * inv * lo32(gamma), db * inv * hi32(gamma));
}

// ======================= K1a: LN(64 rows) + accumulator inits =============
__global__ __launch_bounds__(256) void k_ln(
    const float* __restrict__ x, const float* __restrict__ lna,
    const float* __restrict__ bq, const float* __restrict__ bv) {
    if (blockIdx.x < Rn) {
        __shared__ float sh[8];
        if (blockIdx.x == 0 && threadIdx.x == 0) g_diffsum = 0.f;
        int r = blockIdx.x;
        int b = r >> 4, t = r & 15;
        const float* xr = x + ((size_t)(b * Tn + t)) * Dn;
        int tid = threadIdx.x;
        float v[4];
        float s = 0.f;
#pragma unroll
        for (int i = 0; i < 4; i++) { v[i] = xr[tid + i * 256]; s += v[i]; }
        s = blockReduce256(s, sh);
        float mean = s * (1.f / 1024.f);
        float sq = 0.f;
#pragma unroll
        for (int i = 0; i < 4; i++) { float d = v[i] - mean; sq += d * d; }
        sq = blockReduce256(sq, sh);
        float inv = rsqrtf(sq * (1.f / 1024.f) + 1e-5f);
#pragma unroll
        for (int i = 0; i < 4; i++) {
            int j = tid + i * 256;
            g_xn[r * Dn + j] = (v[i] - mean) * inv * lna[j];
        }
    } else {
        int r = blockIdx.x - Rn;
        int tid = threadIdx.x;
#pragma unroll
        for (int i = 0; i < 4; i++) {
            int j = tid + i * 256;
            g_q[r * Dn + j] = bq[j] * QK_SCALE;
            g_k[r * Dn + j] = 0.f;
            g_v[r * Dn + j] = bv[j];
        }
    }
}

// ======================= K1b: bo fill of whole output (side stream) =======
__global__ __launch_bounds__(256) void k_fill(
    const float* __restrict__ bo, float* __restrict__ out) {
    const float4* bo4 = (const float4*)bo;
    float4* o4 = (float4*)out;
    size_t total = (size_t)Bn * Tn * Dn / 4;
    size_t start = (size_t)blockIdx.x * 256 + threadIdx.x;
    size_t stride = (size_t)gridDim.x * 256;
    float4 v = bo4[start & 255];
    for (size_t i = start; i < total; i += stride) o4[i] = v;
}

// ======================= 64x128 FFMA2 GEMM tile core ======================
#define TK 64

__device__ __forceinline__ void stage_tile(
    const float* __restrict__ A, const float* __restrict__ W,
    int j0, int kb, float* sA, float* sW) {
    int tid = threadIdx.x;
#pragma unroll
    for (int c = tid; c < 64 * TK / 2; c += 128) {
        int r = c >> 5;
        int kf = (c & 31) * 2;
        int rg = r >> 3;
        int swz = ((rg & 3) * 8) | ((rg >> 2) * 2);
        cp8(smem_u32p(&sA[r * TK + (kf ^ swz)]),
            &A[(size_t)r * Dn + kb + kf]);
    }
#pragma unroll
    for (int c = tid; c < 128 * TK / 4; c += 128) {
        int r = c >> 4;
        int kf = (c & 15) * 4;
        cp16(smem_u32p(&sW[r * TK + kf]),
             &W[(size_t)(j0 + r) * Dn + kb + kf]);
    }
    cp_commit();
}

__device__ __forceinline__ void compute_tile(
    const float* sA, const float* sW, u64* acc, int rg, int cg) {
    int swz = ((rg & 3) * 8) | ((rg >> 2) * 2);
    const float* aBase = sA + rg * 8 * TK;
    const float* wBase = sW + cg * 8 * TK;
#pragma unroll 4
    for (int kk = 0; kk < TK; kk += 2) {
        int ka = kk ^ swz;
        u64 av[8], wv[8];
#pragma unroll
        for (int i = 0; i < 8; i++)
            av[i] = *(const u64*)&aBase[i * TK + ka];
#pragma unroll
        for (int j = 0; j < 8; j++)
            wv[j] = *(const u64*)&wBase[j * TK + kk];
#pragma unroll
        for (int i = 0; i < 8; i++)
#pragma unroll
            for (int j = 0; j < 8; j++) ffma2(acc[i * 8 + j], av[i], wv[j]);
    }
}
#define GEMM_SMEM ((64 + 128) * TK * 4)   // 49152 bytes

// ======================= K2: q,k,v GEMMs (k-split 16, red.v4) =============
__global__ __launch_bounds__(128) void k_qkv(
    const float* __restrict__ Wq, const float* __restrict__ Wk,
    const float* __restrict__ Wv) {
    extern __shared__ float sh[];
    float* sA = sh;
    float* sW = sh + 64 * TK;
    int m = blockIdx.z;
    const float* W = (m == 0) ? Wq : (m == 1) ? Wk : Wv;
    float* dst = (m == 0) ? g_q : (m == 1) ? g_k : g_v;
    float scale = (m == 2) ? 1.0f : QK_SCALE;
    int j0 = blockIdx.x * 128;
    int kb = blockIdx.y * TK;
    u64 acc[64] = {};
    stage_tile(g_xn, W, j0, kb, sA, sW);
    cp_wait0();
    __syncthreads();
    int tid = threadIdx.x, rg = tid & 7, cg = tid >> 3;
    compute_tile(sA, sW, acc, rg, cg);
    int c0 = j0 + cg * 8;
#pragma unroll
    for (int i = 0; i < 8; i++) {
        int row = rg * 8 + i;
        float v[8];
#pragma unroll
        for (int j = 0; j < 8; j++) {
            float2 f = *(float2*)&acc[i * 8 + j];
            v[j] = (f.x + f.y) * scale;
        }
        float* p = &dst[(size_t)row * Dn + c0];
        red4(p, v[0], v[1], v[2], v[3]);
        red4(p + 4, v[4], v[5], v[6], v[7]);
    }
}

// ======================= K3a: full k/v recurrence, one kernel =============
// 64 blocks; block handles 16 k-rows AND 16 v-rows (rows r0..r0+15).
// Warps 0-3: k (4 rows each); warps 4-7: v. Rows live in warp-private smem
// -> recurrence needs only __syncwarp. Weights staged once.
__global__ __launch_bounds__(256, 1) void k_KV(
    const float* __restrict__ Wlk, const float* __restrict__ blk,
    const float* __restrict__ Wlv, const float* __restrict__ blv,
    const float* __restrict__ lnd) {
    __shared__ u64 swk[64 * 33];
    __shared__ u64 swv[64 * 33];
    __shared__ u64 sx[32 * 33];       // 16 k rows then 16 v rows
    int tid = threadIdx.x, lane = tid & 31, w = tid >> 5;
    int r0 = blockIdx.x * 16;
    for (int i = tid; i < 2048; i += 256) {
        int j = i >> 5, s = i & 31;
        cp8(smem_u32p(&swk[j * 33 + s]), &Wlk[j * 64 + 2 * s]);
        cp8(smem_u32p(&swv[j * 33 + s]), &Wlv[j * 64 + 2 * s]);
    }
    for (int i = tid; i < 1024; i += 256) {
        int r = i >> 5, s = i & 31;   // r in [0,32)
        const float* src = (r < 16) ? &g_k[(size_t)(r0 + r) * 64 + 2 * s]
                                    : &g_v[(size_t)(r0 + r - 16) * 64 + 2 * s];
        cp8(smem_u32p(&sx[r * 33 + s]), src);
    }
    cp_commit();
    bool isK = (w < 4);
    int wl = isK ? w : w - 4;         // 0..3, owns 4 rows wl*4..wl*4+3
    const u64* sw = isK ? swk : swv;
    const float* blp = isK ? blk : blv;
    u64 bl_p = *(const u64*)&blp[2 * lane];
    u64 lnd_p = *(const u64*)&lnd[2 * lane];
    cp_wait0();
    __syncthreads();
    int xr0 = (isK ? 0 : 16) + wl * 4;
    const u64* w0p = &sw[(2 * lane) * 33];
    const u64* w1p = w0p + 33;

    for (int it = 0; it < 3; it++) {
        u64 acc[4][2] = {};
#pragma unroll 4
        for (int s = 0; s < 32; s++) {
            u64 w0 = w0p[s], w1 = w1p[s];
#pragma unroll
            for (int rr = 0; rr < 4; rr++) {
                u64 xb = sx[(xr0 + rr) * 33 + s];
                ffma2(acc[rr][0], xb, w0);
                ffma2(acc[rr][1], xb, w1);
            }
        }
        __syncwarp();                 // reads done before overwrite
#pragma unroll
        for (int rr = 0; rr < 4; rr++) {
            u64 pair = pack2(lo32(acc[rr][0]) + hi32(acc[rr][0]) + lo32(bl_p),
                             lo32(acc[rr][1]) + hi32(acc[rr][1]) + hi32(bl_p));
            sx[(xr0 + rr) * 33 + lane] = pair;
            int grow = r0 + wl * 4 + rr;
            size_t g = (size_t)it * 65536 + (size_t)grow * 64 + 2 * lane;
            if (isK) *(u64*)&g_ks[g] = ln_pair(pair, lnd_p, 1.0f);
            else     *(u64*)&g_vl[g] = pair;
        }
        __syncwarp();                 // writes visible before next reads
    }
}

// ======================= K3b: per-head q-chain + attention, one kernel ====
// 64 blocks (one per (b,h)); 3 internal iterations. Wlq staged once; qcur
// lives in smem (warp-private rows); ks/vl[it] prefetched via cp.async
// during the q-GEMV. Warp w owns e-rows {w, w+8}.
__global__ __launch_bounds__(256, 1) void k_QAtt(
    const float* __restrict__ Wlq, const float* __restrict__ blq,
    const float* __restrict__ lnc, const float* __restrict__ temp_p) {
    __shared__ u64 swq[64 * 33];
    __shared__ u64 sx[16 * 33];       // qcur
    __shared__ u64 sq[16 * 33];       // LN'd qs
    __shared__ u64 sk[16 * 33];       // ks[it]
    __shared__ u64 sv[16 * 33];       // vl[it]
    __shared__ float red[8];
    int tid = threadIdx.x, lane = tid & 31, w = tid >> 5;
    int bb = blockIdx.x >> 4, h = blockIdx.x & 15;
    for (int i = tid; i < 2048; i += 256) {
        int j = i >> 5, s = i & 31;
        cp8(smem_u32p(&swq[j * 33 + s]), &Wlq[j * 64 + 2 * s]);
    }
    for (int i = tid; i < 512; i += 256) {
        int e = i >> 5, s = i & 31;
        cp8(smem_u32p(&sx[e * 33 + s]),
            &g_q[((size_t)((bb * 16 + e) * 16 + h)) * 64 + 2 * s]);
    }
    cp_commit();
    u64 blq_p = *(const u64*)&blq[2 * lane];
    u64 lnc_p = *(const u64*)&lnc[2 * lane];
    float temp0 = temp_p[0];
    int e0 = w, e1 = w + 8;
    int f = lane & 15, dh = lane >> 4;
    u64 ap0 = 0, ap1 = 0;
    const u64* w0p = &swq[(2 * lane) * 33];
    const u64* w1p = w0p + 33;
    cp_wait0();
    __syncthreads();

    for (int it = 0; it < 3; it++) {
        // prefetch this iteration's ks/vl while doing the q-GEMV
        for (int i = tid; i < 512; i += 256) {
            int e = i >> 5, s = i & 31;
            size_t g = (size_t)it * 65536 +
                       ((size_t)((bb * 16 + e) * 16 + h)) * 64 + 2 * s;
            cp8(smem_u32p(&sk[e * 33 + s]), &g_ks[g]);
            cp8(smem_u32p(&sv[e * 33 + s]), &g_vl[g]);
        }
        cp_commit();

        // ---- q-GEMV: rows e0,e1 ----
        u64 a00 = 0, a01 = 0, a10 = 0, a11 = 0;
#pragma unroll 4
        for (int s = 0; s < 32; s++) {
            u64 w0 = w0p[s], w1 = w1p[s];
            u64 x0 = sx[e0 * 33 + s];
            u64 x1 = sx[e1 * 33 + s];
            ffma2(a00, x0, w0); ffma2(a01, x0, w1);
            ffma2(a10, x1, w0); ffma2(a11, x1, w1);
        }
        u64 ql0 = pack2(lo32(a00) + hi32(a00) + lo32(blq_p),
                        lo32(a01) + hi32(a01) + hi32(blq_p));
        u64 ql1 = pack2(lo32(a10) + hi32(a10) + lo32(blq_p),
                        lo32(a11) + hi32(a11) + hi32(blq_p));
        float t_it = temp0 + 0.005f * (float)it;
        float tsc = ((t_it != 1.0f) && (t_it > 0.f)) ? rsqrtf(t_it) : 1.0f;
        float sc = tsc * SM_SCALE;
        sq[e0 * 33 + lane] = ln_pair(ql0, lnc_p, sc);
        sq[e1 * 33 + lane] = ln_pair(ql1, lnc_p, sc);
        cp_wait0();
        __syncthreads();              // qs published, ks/vl arrived

        // ---- logits (rows e0,e1 vs col f, d-half dh) ----
        u64 acc0 = 0, acc1 = 0;
#pragma unroll
        for (int s = 0; s < 16; s++) {
            int p = dh * 16 + s;
            u64 kv = sk[f * 33 + p];
            ffma2(acc0, sq[e0 * 33 + p], kv);
            ffma2(acc1, sq[e1 * 33 + p], kv);
        }
        float lg0 = lo32(acc0) + hi32(acc0);
        float lg1 = lo32(acc1) + hi32(acc1);
        lg0 += __shfl_xor_sync(0xffffffffu, lg0, 16);
        lg1 += __shfl_xor_sync(0xffffffffu, lg1, 16);
        float mx0 = lg0, mx1 = lg1;
#pragma unroll
        for (int o = 8; o > 0; o >>= 1) {
            mx0 = fmaxf(mx0, __shfl_xor_sync(0xffffffffu, mx0, o, 16));
            mx1 = fmaxf(mx1, __shfl_xor_sync(0xffffffffu, mx1, o, 16));
        }
        float ex0 = __expf(lg0 - mx0), ex1 = __expf(lg1 - mx1);
        float s0 = ex0, s1 = ex1;
#pragma unroll
        for (int o = 8; o > 0; o >>= 1) {
            s0 += __shfl_xor_sync(0xffffffffu, s0, o, 16);
            s1 += __shfl_xor_sync(0xffffffffu, s1, o, 16);
        }
        float pr0 = __fdividef(ex0, s0), pr1 = __fdividef(ex1, s1);

        // ---- ai = softmax @ vl ----
        u64 av0 = 0, av1 = 0;
#pragma unroll
        for (int s = 0; s < 16; s++) {
            float p0 = __shfl_sync(0xffffffffu, pr0, s);
            float p1 = __shfl_sync(0xffffffffu, pr1, s);
            u64 vv = sv[s * 33 + lane];
            ffma2(av0, pack2(p0, p0), vv);
            ffma2(av1, pack2(p1, p1), vv);
        }

        // ---- bookkeeping ----
        size_t g0 = ((size_t)((bb * 16 + e0) * 16 + h)) * 64 + 2 * lane;
        size_t g1 = ((size_t)((bb * 16 + e1) * 16 + h)) * 64 + 2 * lane;
        if (it == 0) { ap0 = av0; ap1 = av1; }
        if (it == 1) {
            *(u64*)&g_ai1[g0] = av0;
            *(u64*)&g_ai1[g1] = av1;
            float ds = fabsf(lo32(av0) - lo32(ap0)) + fabsf(hi32(av0) - hi32(ap0))
                     + fabsf(lo32(av1) - lo32(ap1)) + fabsf(hi32(av1) - hi32(ap1));
            float tot = blockReduce256(ds, red);
            if (tid == 0) atomicAdd(&g_diffsum, tot);
        } else if (it == 2) {
            *(u64*)&g_ai2[g0] = av0;
            *(u64*)&g_ai2[g1] = av1;
        }
        if (it < 2) {   // qcur += ai (warp-private rows in smem)
            sx[e0 * 33 + lane] = fadd2(sx[e0 * 33 + lane], av0);
            sx[e1 * 33 + lane] = fadd2(sx[e1 * 33 + lane], av1);
        }
        __syncthreads();              // sq/sk/sv reads done before next iter
    }
}

// ======================= K4: select ai, Wo proj, red.v4 into out ==========
__global__ __launch_bounds__(128) void k_out(
    const float* __restrict__ Wo, const float* __restrict__ thrp,
    const float* __restrict__ facp, float* __restrict__ out) {
    extern __shared__ float sh[];
    float* sA = sh;
    float* sW = sh + 64 * TK;
    float diff1 = g_diffsum * (1.0f / 8388608.0f);  // mean over B*H*T*hd
    const float* A = (diff1 < thrp[0] + facp[0] * diff1) ? g_ai1 : g_ai2;
    int j0 = blockIdx.x * 128;
    int kb = blockIdx.y * TK;
    u64 acc[64] = {};
    stage_tile(A, Wo, j0, kb, sA, sW);
    cp_wait0();
    __syncthreads();
    int tid = threadIdx.x, rg = tid & 7, cg = tid >> 3;
    compute_tile(sA, sW, acc, rg, cg);
    int c0 = j0 + cg * 8;
#pragma unroll
    for (int i = 0; i < 8; i++) {
        int row = rg * 8 + i;
        int b = row >> 4, t = row & 15;
        float v[8];
#pragma unroll
        for (int j = 0; j < 8; j++) {
            float2 f = *(float2*)&acc[i * 8 + j];
            v[j] = f.x + f.y;
        }
        float* p = &out[((size_t)(b * Tn + t)) * Dn + c0];
        red4(p, v[0], v[1], v[2], v[3]);
        red4(p + 4, v[4], v[5], v[6], v[7]);
    }
}

// ======================= launch ===========================================
extern "C" void kernel_launch(void* const* d_in, const int* in_sizes, int n_in,
                              void* d_out, int out_size) {
    (void)in_sizes; (void)n_in; (void)out_size;
    const float* x    = (const float*)d_in[0];
    const float* Wq   = (const float*)d_in[1];
    const float* bq   = (const float*)d_in[2];
    const float* Wk   = (const float*)d_in[3];
    const float* Wv   = (const float*)d_in[4];
    const float* bv   = (const float*)d_in[5];
    const float* Wo   = (const float*)d_in[6];
    const float* bo   = (const float*)d_in[7];
    const float* lna  = (const float*)d_in[8];
    const float* lnc  = (const float*)d_in[9];
    const float* lnd  = (const float*)d_in[10];
    const float* Wlq  = (const float*)d_in[11];
    const float* blq  = (const float*)d_in[12];
    const float* Wlk  = (const float*)d_in[13];
    const float* blk  = (const float*)d_in[14];
    const float* Wlv  = (const float*)d_in[15];
    const float* blv  = (const float*)d_in[16];
    const float* temp = (const float*)d_in[17];
    const float* thr  = (const float*)d_in[18];
    const float* fac  = (const float*)d_in[19];
    float* out = (float*)d_out;

    static cudaStream_t s2 = nullptr;
    static cudaEvent_t evF = nullptr, evJ = nullptr;
    static bool attrs_set = false;
    if (s2 == nullptr) {
        cudaStreamCreateWithFlags(&s2, cudaStreamNonBlocking);
        cudaEventCreateWithFlags(&evF, cudaEventDisableTiming);
        cudaEventCreateWithFlags(&evJ, cudaEventDisableTiming);
    }
    if (!attrs_set) {
        cudaFuncSetAttribute(k_qkv, cudaFuncAttributeMaxDynamicSharedMemorySize, GEMM_SMEM);
        cudaFuncSetAttribute(k_out, cudaFuncAttributeMaxDynamicSharedMemorySize, GEMM_SMEM);
        attrs_set = true;
    }

    // fork: bo-fill runs concurrently on s2
    cudaEventRecord(evF, 0);
    cudaStreamWaitEvent(s2, evF, 0);
    k_fill<<<1024, 256, 0, s2>>>(bo, out);

    // main chain on stream 0
    k_ln<<<128, 256>>>(x, lna, bq, bv);
    k_qkv<<<dim3(8, 16, 3), 128, GEMM_SMEM>>>(Wq, Wk, Wv);
    k_KV<<<64, 256>>>(Wlk, blk, Wlv, blv, lnd);
    k_QAtt<<<64, 256>>>(Wlq, blq, lnc, temp);

    // join fill before final projection (which red.adds into out)
    cudaEventRecord(evJ, s2);
    cudaStreamWaitEvent(0, evJ, 0);
    k_out<<<dim3(8, 16), 128, GEMM_SMEM>>>(Wo, thr, fac, out);
}

// round 13
// speedup vs baseline: 1.6647x; 1.0296x over previous
#include <cuda_runtime.h>
#include <math.h>

#define Bn 4
#define Tn 2048
#define Dn 1024
#define Hn 16
#define HDn 64
#define En 16
#define Rn 64                     // Bn*En active rows
#define QK_SCALE 0.35355339059327373f   // hd^-0.25
#define SM_SCALE 0.125f                 // 1/sqrt(hd)

typedef unsigned long long u64;

// ---------------- scratch (static device globals; no allocation) ----------
__device__ float g_xn[Rn * Dn];
__device__ float g_q[Rn * Dn];     // q init (post-bias/scale), flat [1024][64]
__device__ float g_k[Rn * Dn];     // k init
__device__ float g_v[Rn * Dn];     // v init
__device__ float g_ks[3 * 65536];  // LN'd kl per iteration
__device__ float g_vl[3 * 65536];  // vl per iteration
__device__ float g_ai1[Rn * Dn];
__device__ float g_ai2[Rn * Dn];
__device__ float g_diffsum;

// ---------------- helpers -------------------------------------------------
__device__ __forceinline__ float warpReduceSum(float v) {
#pragma unroll
    for (int o = 16; o > 0; o >>= 1) v += __shfl_xor_sync(0xffffffffu, v, o);
    return v;
}

__device__ __forceinline__ float blockReduce256(float v, float* sh) {
    __syncthreads();
    v = warpReduceSum(v);
    int wid = threadIdx.x >> 5;
    if ((threadIdx.x & 31) == 0) sh[wid] = v;
    __syncthreads();
    if (threadIdx.x < 32) {
        float t = (threadIdx.x < 8) ? sh[threadIdx.x] : 0.f;
        t = warpReduceSum(t);
        if (threadIdx.x == 0) sh[0] = t;
    }
    __syncthreads();
    return sh[0];
}

// packed fp32x2 FMA (sm_100+)
__device__ __forceinline__ void ffma2(u64& d, u64 a, u64 b) {
    asm("fma.rn.f32x2 %0, %1, %2, %0;" : "+l"(d) : "l"(a), "l"(b));
}
__device__ __forceinline__ u64 fadd2(u64 a, u64 b) {
    u64 r;
    asm("add.rn.f32x2 %0, %1, %2;" : "=l"(r) : "l"(a), "l"(b));
    return r;
}
__device__ __forceinline__ u64 pack2(float a, float b) {
    u64 r;
    asm("mov.b64 %0, {%1, %2};" : "=l"(r) : "f"(a), "f"(b));
    return r;
}
__device__ __forceinline__ float lo32(u64 v) { return ((float2*)&v)->x; }
__device__ __forceinline__ float hi32(u64 v) { return ((float2*)&v)->y; }

__device__ __forceinline__ unsigned smem_u32p(const void* p) {
    return (unsigned)__cvta_generic_to_shared(p);
}
__device__ __forceinline__ void cp16(unsigned dst, const void* src) {
    asm volatile("cp.async.cg.shared.global [%0], [%1], 16;" :: "r"(dst), "l"(src));
}
__device__ __forceinline__ void cp8(unsigned dst, const void* src) {
    asm volatile("cp.async.ca.shared.global [%0], [%1], 8;" :: "r"(dst), "l"(src));
}
__device__ __forceinline__ void cp_commit() {
    asm volatile("cp.async.commit_group;");
}
__device__ __forceinline__ void cp_wait0() {
    asm volatile("cp.async.wait_group 0;");
}
// vector float atomic add (sm_90+)
__device__ __forceinline__ void red4(float* p, float a, float b, float c, float d) {
    asm volatile("red.global.add.v4.f32 [%0], {%1,%2,%3,%4};"
                 :: "l"(p), "f"(a), "f"(b), "f"(c), "f"(d) : "memory");
}

// full-warp LN over 64 elements held as one f32x2 pair per lane
__device__ __forceinline__ u64 ln_pair(u64 y, u64 gamma, float scale) {
    float a = lo32(y), b = hi32(y);
    float s = a + b;
#pragma unroll
    for (int o = 16; o > 0; o >>= 1) s += __shfl_xor_sync(0xffffffffu, s, o);
    float mean = s * (1.f / 64.f);
    float da = a - mean, db = b - mean;
    float q = da * da + db * db;
#pragma unroll
    for (int o = 16; o > 0; o >>= 1) q += __shfl_xor_sync(0xffffffffu, q, o);
    float inv = rsqrtf(q * (1.f / 64.f) + 1e-5f) * scale;
    return pack2(da * inv * lo32(gamma), db * inv * hi32(gamma));
}

// ======================= K1a: LN(64 rows) + accumulator inits =============
__global__ __launch_bounds__(256) void k_ln(
    const float* __restrict__ x, const float* __restrict__ lna,
    const float* __restrict__ bq, const float* __restrict__ bv) {
    if (blockIdx.x < Rn) {
        __shared__ float sh[8];
        if (blockIdx.x == 0 && threadIdx.x == 0) g_diffsum = 0.f;
        int r = blockIdx.x;
        int b = r >> 4, t = r & 15;
        const float* xr = x + ((size_t)(b * Tn + t)) * Dn;
        int tid = threadIdx.x;
        float v[4];
        float s = 0.f;
#pragma unroll
        for (int i = 0; i < 4; i++) { v[i] = xr[tid + i * 256]; s += v[i]; }
        s = blockReduce256(s, sh);
        float mean = s * (1.f / 1024.f);
        float sq = 0.f;
#pragma unroll
        for (int i = 0; i < 4; i++) { float d = v[i] - mean; sq += d * d; }
        sq = blockReduce256(sq, sh);
        float inv = rsqrtf(sq * (1.f / 1024.f) + 1e-5f);
#pragma unroll
        for (int i = 0; i < 4; i++) {
            int j = tid + i * 256;
            g_xn[r * Dn + j] = (v[i] - mean) * inv * lna[j];
        }
    } else {
        int r = blockIdx.x - Rn;
        int tid = threadIdx.x;
#pragma unroll
        for (int i = 0; i < 4; i++) {
            int j = tid + i * 256;
            g_q[r * Dn + j] = bq[j] * QK_SCALE;
            g_k[r * Dn + j] = 0.f;
            g_v[r * Dn + j] = bv[j];
        }
    }
}

// ======================= K1b: bo fill of whole output (side stream) =======
__global__ __launch_bounds__(256) void k_fill(
    const float* __restrict__ bo, float* __restrict__ out) {
    const float4* bo4 = (const float4*)bo;
    float4* o4 = (float4*)out;
    size_t total = (size_t)Bn * Tn * Dn / 4;
    size_t start = (size_t)blockIdx.x * 256 + threadIdx.x;
    size_t stride = (size_t)gridDim.x * 256;
    float4 v = bo4[start & 255];
    for (size_t i = start; i < total; i += stride) o4[i] = v;
}

// ======================= 64x128 FFMA2 GEMM tile core ======================
#define TK 64

__device__ __forceinline__ void stage_tile(
    const float* __restrict__ A, const float* __restrict__ W,
    int j0, int kb, float* sA, float* sW) {
    int tid = threadIdx.x;
#pragma unroll
    for (int c = tid; c < 64 * TK / 2; c += 128) {
        int r = c >> 5;
        int kf = (c & 31) * 2;
        int rg = r >> 3;
        int swz = ((rg & 3) * 8) | ((rg >> 2) * 2);
        cp8(smem_u32p(&sA[r * TK + (kf ^ swz)]),
            &A[(size_t)r * Dn + kb + kf]);
    }
#pragma unroll
    for (int c = tid; c < 128 * TK / 4; c += 128) {
        int r = c >> 4;
        int kf = (c & 15) * 4;
        cp16(smem_u32p(&sW[r * TK + kf]),
             &W[(size_t)(j0 + r) * Dn + kb + kf]);
    }
    cp_commit();
}

__device__ __forceinline__ void compute_tile(
    const float* sA, const float* sW, u64* acc, int rg, int cg) {
    int swz = ((rg & 3) * 8) | ((rg >> 2) * 2);
    const float* aBase = sA + rg * 8 * TK;
    const float* wBase = sW + cg * 8 * TK;
#pragma unroll 4
    for (int kk = 0; kk < TK; kk += 2) {
        int ka = kk ^ swz;
        u64 av[8], wv[8];
#pragma unroll
        for (int i = 0; i < 8; i++)
            av[i] = *(const u64*)&aBase[i * TK + ka];
#pragma unroll
        for (int j = 0; j < 8; j++)
            wv[j] = *(const u64*)&wBase[j * TK + kk];
#pragma unroll
        for (int i = 0; i < 8; i++)
#pragma unroll
            for (int j = 0; j < 8; j++) ffma2(acc[i * 8 + j], av[i], wv[j]);
    }
}
#define GEMM_SMEM ((64 + 128) * TK * 4)   // 49152 bytes

// ======================= K2: q,k,v GEMMs (k-split 16, red.v4) =============
__global__ __launch_bounds__(128) void k_qkv(
    const float* __restrict__ Wq, const float* __restrict__ Wk,
    const float* __restrict__ Wv) {
    extern __shared__ float sh[];
    float* sA = sh;
    float* sW = sh + 64 * TK;
    int m = blockIdx.z;
    const float* W = (m == 0) ? Wq : (m == 1) ? Wk : Wv;
    float* dst = (m == 0) ? g_q : (m == 1) ? g_k : g_v;
    float scale = (m == 2) ? 1.0f : QK_SCALE;
    int j0 = blockIdx.x * 128;
    int kb = blockIdx.y * TK;
    u64 acc[64] = {};
    stage_tile(g_xn, W, j0, kb, sA, sW);
    cp_wait0();
    __syncthreads();
    int tid = threadIdx.x, rg = tid & 7, cg = tid >> 3;
    compute_tile(sA, sW, acc, rg, cg);
    int c0 = j0 + cg * 8;
#pragma unroll
    for (int i = 0; i < 8; i++) {
        int row = rg * 8 + i;
        float v[8];
#pragma unroll
        for (int j = 0; j < 8; j++) {
            float2 f = *(float2*)&acc[i * 8 + j];
            v[j] = (f.x + f.y) * scale;
        }
        float* p = &dst[(size_t)row * Dn + c0];
        red4(p, v[0], v[1], v[2], v[3]);
        red4(p + 4, v[4], v[5], v[6], v[7]);
    }
}

// ======================= K3a: k/v recurrence (split K/V blocks) ===========
// grid 128: blocks 0..63 = K (rows bx*16..+15), 64..127 = V.
// Weights staged TRANSPOSED: wl[s*64 + j] = W[j][2s..2s+1], so each lane's
// (w0,w1) pair for cols (2l,2l+1) is ONE conflict-free LDS.128.
// 2 rows per warp; rows warp-private in smem -> __syncwarp only.
__global__ __launch_bounds__(256, 1) void k_KV(
    const float* __restrict__ Wlk, const float* __restrict__ blk,
    const float* __restrict__ Wlv, const float* __restrict__ blv,
    const float* __restrict__ lnd) {
    __shared__ u64 wl[2048];          // 16 KB, wl[s*64+j]
    __shared__ u64 sx[16 * 33];
    int tid = threadIdx.x, lane = tid & 31, w = tid >> 5;
    bool isK = (blockIdx.x < 64);
    int r0 = (isK ? blockIdx.x : blockIdx.x - 64) * 16;
    const float* Wm = isK ? Wlk : Wlv;
    const float* blp = isK ? blk : blv;
    const float* src = isK ? g_k : g_v;
    for (int i = tid; i < 2048; i += 256) {
        int j = i >> 5, s = i & 31;
        cp8(smem_u32p(&wl[s * 64 + j]), &Wm[j * 64 + 2 * s]);
    }
    for (int i = tid; i < 512; i += 256) {
        int r = i >> 5, s = i & 31;
        cp8(smem_u32p(&sx[r * 33 + s]), &src[(size_t)(r0 + r) * 64 + 2 * s]);
    }
    cp_commit();
    u64 bl_p = *(const u64*)&blp[2 * lane];
    u64 lnd_p = *(const u64*)&lnd[2 * lane];
    cp_wait0();
    __syncthreads();
    int xr0 = w * 2;

    for (int it = 0; it < 3; it++) {
        u64 acc[2][2] = {};
#pragma unroll 4
        for (int s = 0; s < 32; s++) {
            ulonglong2 wv = *(const ulonglong2*)&wl[s * 64 + 2 * lane];
            u64 x0 = sx[xr0 * 33 + s];
            u64 x1 = sx[(xr0 + 1) * 33 + s];
            ffma2(acc[0][0], x0, wv.x); ffma2(acc[0][1], x0, wv.y);
            ffma2(acc[1][0], x1, wv.x); ffma2(acc[1][1], x1, wv.y);
        }
        __syncwarp();                 // reads done before overwrite
#pragma unroll
        for (int rr = 0; rr < 2; rr++) {
            u64 pair = pack2(lo32(acc[rr][0]) + hi32(acc[rr][0]) + lo32(bl_p),
                             lo32(acc[rr][1]) + hi32(acc[rr][1]) + hi32(bl_p));
            sx[(xr0 + rr) * 33 + lane] = pair;
            size_t g = (size_t)it * 65536 + (size_t)(r0 + xr0 + rr) * 64 + 2 * lane;
            if (isK) *(u64*)&g_ks[g] = ln_pair(pair, lnd_p, 1.0f);
            else     *(u64*)&g_vl[g] = pair;
        }
        __syncwarp();                 // writes visible before next reads
    }
}

// ======================= K3b: per-head q-chain + attention, one kernel ====
// 64 blocks (one per (b,h)); 3 internal iterations. Wlq staged once
// (transposed, conflict-free LDS.128); qcur in smem; ks/vl[it] prefetched
// via cp.async during the q-GEMV. Warp w owns e-rows {w, w+8}.
__global__ __launch_bounds__(256, 1) void k_QAtt(
    const float* __restrict__ Wlq, const float* __restrict__ blq,
    const float* __restrict__ lnc, const float* __restrict__ temp_p) {
    __shared__ u64 wl[2048];          // wl[s*64+j]
    __shared__ u64 sx[16 * 33];       // qcur
    __shared__ u64 sq[16 * 33];       // LN'd qs
    __shared__ u64 sk[16 * 33];       // ks[it]
    __shared__ u64 sv[16 * 33];       // vl[it]
    __shared__ float red[8];
    int tid = threadIdx.x, lane = tid & 31, w = tid >> 5;
    int bb = blockIdx.x >> 4, h = blockIdx.x & 15;
    for (int i = tid; i < 2048; i += 256) {
        int j = i >> 5, s = i & 31;
        cp8(smem_u32p(&wl[s * 64 + j]), &Wlq[j * 64 + 2 * s]);
    }
    for (int i = tid; i < 512; i += 256) {
        int e = i >> 5, s = i & 31;
        cp8(smem_u32p(&sx[e * 33 + s]),
            &g_q[((size_t)((bb * 16 + e) * 16 + h)) * 64 + 2 * s]);
    }
    cp_commit();
    u64 blq_p = *(const u64*)&blq[2 * lane];
    u64 lnc_p = *(const u64*)&lnc[2 * lane];
    float temp0 = temp_p[0];
    int e0 = w, e1 = w + 8;
    int f = lane & 15, dh = lane >> 4;
    u64 ap0 = 0, ap1 = 0;
    cp_wait0();
    __syncthreads();

    for (int it = 0; it < 3; it++) {
        // prefetch this iteration's ks/vl while doing the q-GEMV
        for (int i = tid; i < 512; i += 256) {
            int e = i >> 5, s = i & 31;
            size_t g = (size_t)it * 65536 +
                       ((size_t)((bb * 16 + e) * 16 + h)) * 64 + 2 * s;
            cp8(smem_u32p(&sk[e * 33 + s]), &g_ks[g]);
            cp8(smem_u32p(&sv[e * 33 + s]), &g_vl[g]);
        }
        cp_commit();

        // ---- q-GEMV: rows e0,e1, conflict-free weight LDS.128 ----
        u64 a00 = 0, a01 = 0, a10 = 0, a11 = 0;
#pragma unroll 4
        for (int s = 0; s < 32; s++) {
            ulonglong2 wv = *(const ulonglong2*)&wl[s * 64 + 2 * lane];
            u64 x0 = sx[e0 * 33 + s];
            u64 x1 = sx[e1 * 33 + s];
            ffma2(a00, x0, wv.x); ffma2(a01, x0, wv.y);
            ffma2(a10, x1, wv.x); ffma2(a11, x1, wv.y);
        }
        u64 ql0 = pack2(lo32(a00) + hi32(a00) + lo32(blq_p),
                        lo32(a01) + hi32(a01) + hi32(blq_p));
        u64 ql1 = pack2(lo32(a10) + hi32(a10) + lo32(blq_p),
                        lo32(a11) + hi32(a11) + hi32(blq_p));
        float t_it = temp0 + 0.005f * (float)it;
        float tsc = ((t_it != 1.0f) && (t_it > 0.f)) ? rsqrtf(t_it) : 1.0f;
        float sc = tsc * SM_SCALE;
        sq[e0 * 33 + lane] = ln_pair(ql0, lnc_p, sc);
        sq[e1 * 33 + lane] = ln_pair(ql1, lnc_p, sc);
        cp_wait0();
        __syncthreads();              // qs published, ks/vl arrived

        // ---- logits (rows e0,e1 vs col f, d-half dh) ----
        u64 acc0 = 0, acc1 = 0;
#pragma unroll
        for (int s = 0; s < 16; s++) {
            int p = dh * 16 + s;
            u64 kv = sk[f * 33 + p];
            ffma2(acc0, sq[e0 * 33 + p], kv);
            ffma2(acc1, sq[e1 * 33 + p], kv);
        }
        float lg0 = lo32(acc0) + hi32(acc0);
        float lg1 = lo32(acc1) + hi32(acc1);
        lg0 += __shfl_xor_sync(0xffffffffu, lg0, 16);
        lg1 += __shfl_xor_sync(0xffffffffu, lg1, 16);
        float mx0 = lg0, mx1 = lg1;
#pragma unroll
        for (int o = 8; o > 0; o >>= 1) {
            mx0 = fmaxf(mx0, __shfl_xor_sync(0xffffffffu, mx0, o, 16));
            mx1 = fmaxf(mx1, __shfl_xor_sync(0xffffffffu, mx1, o, 16));
        }
        float ex0 = __expf(lg0 - mx0), ex1 = __expf(lg1 - mx1);
        float s0 = ex0, s1 = ex1;
#pragma unroll
        for (int o = 8; o > 0; o >>= 1) {
            s0 += __shfl_xor_sync(0xffffffffu, s0, o, 16);
            s1 += __shfl_xor_sync(0xffffffffu, s1, o, 16);
        }
        float pr0 = __fdividef(ex0, s0), pr1 = __fdividef(ex1, s1);

        // ---- ai = softmax @ vl ----
        u64 av0 = 0, av1 = 0;
#pragma unroll
        for (int s = 0; s < 16; s++) {
            float p0 = __shfl_sync(0xffffffffu, pr0, s);
            float p1 = __shfl_sync(0xffffffffu, pr1, s);
            u64 vv = sv[s * 33 + lane];
            ffma2(av0, pack2(p0, p0), vv);
            ffma2(av1, pack2(p1, p1), vv);
        }

        // ---- bookkeeping ----
        size_t g0 = ((size_t)((bb * 16 + e0) * 16 + h)) * 64 + 2 * lane;
        size_t g1 = ((size_t)((bb * 16 + e1) * 16 + h)) * 64 + 2 * lane;
        if (it == 0) { ap0 = av0; ap1 = av1; }
        if (it == 1) {
            *(u64*)&g_ai1[g0] = av0;
            *(u64*)&g_ai1[g1] = av1;
            float ds = fabsf(lo32(av0) - lo32(ap0)) + fabsf(hi32(av0) - hi32(ap0))
                     + fabsf(lo32(av1) - lo32(ap1)) + fabsf(hi32(av1) - hi32(ap1));
            float tot = blockReduce256(ds, red);
            if (tid == 0) atomicAdd(&g_diffsum, tot);
        } else if (it == 2) {
            *(u64*)&g_ai2[g0] = av0;
            *(u64*)&g_ai2[g1] = av1;
        }
        if (it < 2) {   // qcur += ai (warp-private rows in smem)
            sx[e0 * 33 + lane] = fadd2(sx[e0 * 33 + lane], av0);
            sx[e1 * 33 + lane] = fadd2(sx[e1 * 33 + lane], av1);
        }
        __syncthreads();              // sq/sk/sv reads done before next iter
    }
}

// ======================= K4: select ai, Wo proj, red.v4 into out ==========
__global__ __launch_bounds__(128) void k_out(
    const float* __restrict__ Wo, const float* __restrict__ thrp,
    const float* __restrict__ facp, float* __restrict__ out) {
    extern __shared__ float sh[];
    float* sA = sh;
    float* sW = sh + 64 * TK;
    float diff1 = g_diffsum * (1.0f / 8388608.0f);  // mean over B*H*T*hd
    const float* A = (diff1 < thrp[0] + facp[0] * diff1) ? g_ai1 : g_ai2;
    int j0 = blockIdx.x * 128;
    int kb = blockIdx.y * TK;
    u64 acc[64] = {};
    stage_tile(A, Wo, j0, kb, sA, sW);
    cp_wait0();
    __syncthreads();
    int tid = threadIdx.x, rg = tid & 7, cg = tid >> 3;
    compute_tile(sA, sW, acc, rg, cg);
    int c0 = j0 + cg * 8;
#pragma unroll
    for (int i = 0; i < 8; i++) {
        int row = rg * 8 + i;
        int b = row >> 4, t = row & 15;
        float v[8];
#pragma unroll
        for (int j = 0; j < 8; j++) {
            float2 f = *(float2*)&acc[i * 8 + j];
            v[j] = f.x + f.y;
        }
        float* p = &out[((size_t)(b * Tn + t)) * Dn + c0];
        red4(p, v[0], v[1], v[2], v[3]);
        red4(p + 4, v[4], v[5], v[6], v[7]);
    }
}

// ======================= launch ===========================================
extern "C" void kernel_launch(void* const* d_in, const int* in_sizes, int n_in,
                              void* d_out, int out_size) {
    (void)in_sizes; (void)n_in; (void)out_size;
    const float* x    = (const float*)d_in[0];
    const float* Wq   = (const float*)d_in[1];
    const float* bq   = (const float*)d_in[2];
    const float* Wk   = (const float*)d_in[3];
    const float* Wv   = (const float*)d_in[4];
    const float* bv   = (const float*)d_in[5];
    const float* Wo   = (const float*)d_in[6];
    const float* bo   = (const float*)d_in[7];
    const float* lna  = (const float*)d_in[8];
    const float* lnc  = (const float*)d_in[9];
    const float* lnd  = (const float*)d_in[10];
    const float* Wlq  = (const float*)d_in[11];
    const float* blq  = (const float*)d_in[12];
    const float* Wlk  = (const float*)d_in[13];
    const float* blk  = (const float*)d_in[14];
    const float* Wlv  = (const float*)d_in[15];
    const float* blv  = (const float*)d_in[16];
    const float* temp = (const float*)d_in[17];
    const float* thr  = (const float*)d_in[18];
    const float* fac  = (const float*)d_in[19];
    float* out = (float*)d_out;

    static cudaStream_t s2 = nullptr;
    static cudaEvent_t evF = nullptr, evJ = nullptr;
    static bool attrs_set = false;
    if (s2 == nullptr) {
        cudaStreamCreateWithFlags(&s2, cudaStreamNonBlocking);
        cudaEventCreateWithFlags(&evF, cudaEventDisableTiming);
        cudaEventCreateWithFlags(&evJ, cudaEventDisableTiming);
    }
    if (!attrs_set) {
        cudaFuncSetAttribute(k_qkv, cudaFuncAttributeMaxDynamicSharedMemorySize, GEMM_SMEM);
        cudaFuncSetAttribute(k_out, cudaFuncAttributeMaxDynamicSharedMemorySize, GEMM_SMEM);
        attrs_set = true;
    }

    // fork: bo-fill runs concurrently on s2
    cudaEventRecord(evF, 0);
    cudaStreamWaitEvent(s2, evF, 0);
    k_fill<<<1024, 256, 0, s2>>>(bo, out);

    // main chain on stream 0
    k_ln<<<128, 256>>>(x, lna, bq, bv);
    k_qkv<<<dim3(8, 16, 3), 128, GEMM_SMEM>>>(Wq, Wk, Wv);
    k_KV<<<128, 256>>>(Wlk, blk, Wlv, blv, lnd);
    k_QAtt<<<64, 256>>>(Wlq, blq, lnc, temp);

    // join fill before final projection (which red.adds into out)
    cudaEventRecord(evJ, s2);
    cudaStreamWaitEvent(0, evJ, 0);
    k_out<<<dim3(8, 16), 128, GEMM_SMEM>>>(Wo, thr, fac, out);
}